// round 9
// baseline (speedup 1.0000x reference)
#include <cuda_runtime.h>
#include <cuda_fp16.h>

#define BB 256
#define II 1152
#define OO 10
#define DDO 16
#define DDI 8
#define OD 160       // OO*DDO

// k_hat tiling
#define ITH 16       // i per block (hat)
#define NTH 72       // II/ITH
// k_route tiling
#define ITR 64       // i per block (route)
#define NTR 18       // II/ITR
#define NTMAX 72     // g_spart tile stride

// Scratch (device globals: allocation-free rule)
__device__ __half g_hat[(size_t)BB * II * OD];    // ~94.4 MB
__device__ float g_spart[(size_t)BB * NTMAX * OD];
__device__ float g_vsum[BB * OD];

// K1: hat = W @ x per (b,i). No smem, no barriers: W rows via L1-hot LDG
// (8 warps/block share W[i]); x via broadcast LDG. Warp handles 4 batches.
__global__ void __launch_bounds__(256) k_hat(const float* __restrict__ x,
                                             const float* __restrict__ w) {
    const int t = threadIdx.x;
    const int warp = t >> 5, lane = t & 31;
    const int og = lane >> 4, d = lane & 15;
    const int i0 = blockIdx.x * ITH;
    const int b0 = blockIdx.y * 32 + warp * 4;   // 4 batches per warp

    float sacc[4][5];
    #pragma unroll
    for (int bi = 0; bi < 4; bi++)
        #pragma unroll
        for (int j = 0; j < 5; j++) sacc[bi][j] = 0.f;

    for (int ii = 0; ii < ITH; ii++) {
        const int i = i0 + ii;
        float4 xa[4], xb[4];
        #pragma unroll
        for (int bi = 0; bi < 4; bi++) {
            const float* xp = x + ((size_t)(b0 + bi) * II + i) * DDI;
            xa[bi] = __ldg((const float4*)xp);
            xb[bi] = __ldg((const float4*)(xp + 4));
        }
        const float* wi = w + (size_t)i * (OD * DDI);
        __half* hp0 = g_hat + ((size_t)b0 * II + i) * OD;

        #pragma unroll
        for (int j = 0; j < 5; j++) {
            const int o = og + 2 * j;
            const float* wr = wi + (o * DDO + d) * DDI;
            const float4 wa = __ldg((const float4*)wr);
            const float4 wb = __ldg((const float4*)(wr + 4));
            #pragma unroll
            for (int bi = 0; bi < 4; bi++) {
                float h = wa.x*xa[bi].x + wa.y*xa[bi].y + wa.z*xa[bi].z + wa.w*xa[bi].w
                        + wb.x*xb[bi].x + wb.y*xb[bi].y + wb.z*xb[bi].z + wb.w*xb[bi].w;
                sacc[bi][j] += h;
                hp0[(size_t)bi * (II * OD) + j * 32 + lane] = __float2half_rn(h);
            }
        }
    }
    #pragma unroll
    for (int bi = 0; bi < 4; bi++) {
        float* sp = g_spart + ((size_t)(b0 + bi) * NTMAX + blockIdx.x) * OD;
        #pragma unroll
        for (int j = 0; j < 5; j++) sp[j * 32 + lane] = 0.1f * sacc[bi][j];
    }
}

// K2: routing pass, o-per-lane. Lane = (bh, o): lanes 0-9 & 16-25 active.
__global__ void __launch_bounds__(256) k_route() {
    const int t = threadIdx.x;
    const int warp = t >> 5, lane = t & 31;
    const int o = lane & 15;
    const bool act = (o < OO);
    const int b = blockIdx.y * 16 + warp * 2 + (lane >> 4);
    const int i0 = blockIdx.x * ITR;

    float v[16];
    const float* vp = g_vsum + b * OD + o * DDO;
    if (act) {
        #pragma unroll
        for (int r = 0; r < 4; r++) {
            float4 f = *(const float4*)(vp + 4 * r);
            v[4*r] = f.x; v[4*r+1] = f.y; v[4*r+2] = f.z; v[4*r+3] = f.w;
        }
    } else {
        #pragma unroll
        for (int k = 0; k < 16; k++) v[k] = 0.f;
    }

    float sacc[16];
    #pragma unroll
    for (int k = 0; k < 16; k++) sacc[k] = 0.f;

    #pragma unroll 2
    for (int ii = 0; ii < ITR; ii++) {
        const __half* hp = g_hat + ((size_t)b * II + (i0 + ii)) * OD + o * DDO;
        float h[16];
        float e = 0.f;
        if (act) {
            uint4 ra = *(const uint4*)hp;
            uint4 rb = *(const uint4*)(hp + 8);
            const __half2* pa = (const __half2*)&ra;
            const __half2* pb = (const __half2*)&rb;
            #pragma unroll
            for (int k = 0; k < 4; k++) {
                float2 fa = __half22float2(pa[k]);
                float2 fb = __half22float2(pb[k]);
                h[2*k]   = fa.x; h[2*k+1]   = fa.y;
                h[8+2*k] = fb.x; h[8+2*k+1] = fb.y;
            }
            float q = 0.f;
            #pragma unroll
            for (int k = 0; k < 16; k++) q += h[k] * v[k];
            e = __expf(q);                      // unstabilized, |q| small
        } else {
            #pragma unroll
            for (int k = 0; k < 16; k++) h[k] = 0.f;
        }
        float tot = e;
        #pragma unroll
        for (int s = 8; s >= 1; s >>= 1)
            tot += __shfl_xor_sync(0xffffffffu, tot, s);
        const float c = e * (1.0f / tot);
        #pragma unroll
        for (int k = 0; k < 16; k++) sacc[k] += c * h[k];
    }

    if (act) {
        float* sp = g_spart + ((size_t)b * NTMAX + blockIdx.x) * OD + o * DDO;
        #pragma unroll
        for (int r = 0; r < 4; r++)
            *(float4*)(sp + 4 * r) = make_float4(sacc[4*r], sacc[4*r+1],
                                                 sacc[4*r+2], sacc[4*r+3]);
    }
}

// K3: fixed-order partial reduction + squash. Warp per (b,o); lane = (tc, d).
__global__ void __launch_bounds__(256) k_squash(float* __restrict__ out, int mode,
                                                int ntiles) {
    const int t = threadIdx.x;
    const int warp = t >> 5, lane = t & 31;
    const int g = blockIdx.x * 8 + warp;       // (b,o), 2560 total
    const int d = lane & 15, tc = lane >> 4;
    const int b = g / OO, o = g - b * OO;
    const int od = o * DDO + d;

    float sh = 0.f;
    for (int tt = tc; tt < ntiles; tt += 2)
        sh += g_spart[((size_t)b * NTMAX + tt) * OD + od];
    const float s = sh + __shfl_xor_sync(0xffffffffu, sh, 16);

    float ss = s * s;
    #pragma unroll
    for (int r = 8; r >= 1; r >>= 1)
        ss += __shfl_xor_sync(0xffffffffu, ss, r);

    const float nrm = sqrtf(ss);
    const float v = s * (nrm / (nrm * nrm + 1.0f));
    if (tc == 0) {
        const int idx = b * OD + od;
        if (mode == 2)      out[idx] = v;
        else if (mode == 1) g_vsum[idx] += v;
        else                g_vsum[idx] = v;
    }
}

// Diagnostic no-op: shifts launch index so ncu (-s 5) profiles route iter 2.
__global__ void k_nop() {}

extern "C" void kernel_launch(void* const* d_in, const int* in_sizes, int n_in,
                              void* d_out, int out_size) {
    const float* x = (const float*)d_in[0];   // (B, I, DI)
    const float* w = (const float*)d_in[1];   // (I*O, DO, DI)
    float* out = (float*)d_out;               // (B, O, DO)

    dim3 ghat(NTH, BB / 32);
    dim3 grt(NTR, BB / 16);

    k_hat<<<ghat, 256>>>(x, w);            // 0
    k_squash<<<320, 256>>>(out, 0, NTH);   // 1: v0 -> vsum
    k_route<<<grt, 256>>>();               // 2: iter 1
    k_squash<<<320, 256>>>(out, 1, NTR);   // 3: v1 -> vsum
    k_nop<<<1, 32>>>();                    // 4: ncu index shim
    k_route<<<grt, 256>>>();               // 5: iter 2  <- profiled
    k_squash<<<320, 256>>>(out, 2, NTR);   // 6: v2 -> out
}

// round 12
// speedup vs baseline: 1.0521x; 1.0521x over previous
#include <cuda_runtime.h>
#include <cuda_fp16.h>

#define BB 256
#define II 1152
#define OO 10
#define DDO 16
#define DDI 8
#define OD 160       // OO*DDO
#define WPR 20       // words per W pair-row (16 data + 4 pad): 80B stride,
                     // 16B-aligned and conflict-free for LDS.128 (stride 20 mod 32)

// k_hat tiling
#define ITH 16       // i per block (hat)
#define NTH 72       // II/ITH
#define RPT 4        // i staged per sync round
// k_route tiling
#define ITR 64       // i per block (route)
#define NTR 18       // II/ITR
#define NTMAX 72     // g_spart tile stride

// Scratch (device globals: allocation-free rule)
__device__ __half g_hat[(size_t)BB * II * OD];    // ~94.4 MB
__device__ float g_spart[(size_t)BB * NTMAX * OD];
__device__ float g_vsum[BB * OD];

// K1: hat = W @ x per (b,i). W staged as 80 pair-rows x 16 floats (stride 20).
// Lane owns od pairs 2*lane(+1), 64+2*lane(+1), and (lane<16) 128+2*lane(+1)
// -> packed half2 stores (full 128B warp bursts). 4 batches per warp.
__global__ void __launch_bounds__(256) k_hat(const float* __restrict__ x,
                                             const float* __restrict__ w) {
    __shared__ float wsm[RPT][80 * WPR];
    const int t = threadIdx.x;
    const int warp = t >> 5, lane = t & 31;
    const int i0 = blockIdx.x * ITH;
    const int b0 = blockIdx.y * 32 + warp * 4;   // 4 batches per warp

    float sacc[4][6];
    #pragma unroll
    for (int bi = 0; bi < 4; bi++)
        #pragma unroll
        for (int j = 0; j < 6; j++) sacc[bi][j] = 0.f;

    for (int rr = 0; rr < ITH / RPT; rr++) {
        const int ib = i0 + rr * RPT;
        #pragma unroll
        for (int im = 0; im < RPT; im++) {
            const float* wp = w + (size_t)(ib + im) * (OD * DDI);
            #pragma unroll
            for (int r = 0; r < 5; r++) {
                int e = t + r * 256;           // e = od*8+k ; pair = e>>4, kk = e&15
                wsm[im][(e >> 4) * WPR + (e & 15)] = wp[e];
            }
        }
        __syncthreads();

        #pragma unroll
        for (int im = 0; im < RPT; im++) {
            const int i = ib + im;
            float4 xa[4], xb[4];
            #pragma unroll
            for (int bi = 0; bi < 4; bi++) {
                const float* xp = x + ((size_t)(b0 + bi) * II + i) * DDI;
                xa[bi] = *(const float4*)xp;
                xb[bi] = *(const float4*)(xp + 4);
            }
            const float* base = wsm[im];
            __half* hp0 = g_hat + ((size_t)b0 * II + i) * OD;

            // j = 0,1 : pair p = lane + 32*j  (all lanes)
            #pragma unroll
            for (int j = 0; j < 2; j++) {
                const int p = lane + 32 * j;
                const float* pr = base + p * WPR;
                const float4 wa0 = *(const float4*)pr;          // even od, k0-3
                const float4 wb0 = *(const float4*)(pr + 4);    // even od, k4-7
                const float4 wa1 = *(const float4*)(pr + 8);    // odd od,  k0-3
                const float4 wb1 = *(const float4*)(pr + 12);   // odd od,  k4-7
                #pragma unroll
                for (int bi = 0; bi < 4; bi++) {
                    float he = wa0.x*xa[bi].x + wa0.y*xa[bi].y + wa0.z*xa[bi].z + wa0.w*xa[bi].w
                             + wb0.x*xb[bi].x + wb0.y*xb[bi].y + wb0.z*xb[bi].z + wb0.w*xb[bi].w;
                    float ho = wa1.x*xa[bi].x + wa1.y*xa[bi].y + wa1.z*xa[bi].z + wa1.w*xa[bi].w
                             + wb1.x*xb[bi].x + wb1.y*xb[bi].y + wb1.z*xb[bi].z + wb1.w*xb[bi].w;
                    sacc[bi][2*j]   += he;
                    sacc[bi][2*j+1] += ho;
                    *(__half2*)(hp0 + (size_t)bi * (II * OD) + 2 * p) =
                        __floats2half2_rn(he, ho);
                }
            }
            // j = 2 : pair p = lane + 64, lanes 0-15 only
            if (lane < 16) {
                const int p = lane + 64;
                const float* pr = base + p * WPR;
                const float4 wa0 = *(const float4*)pr;
                const float4 wb0 = *(const float4*)(pr + 4);
                const float4 wa1 = *(const float4*)(pr + 8);
                const float4 wb1 = *(const float4*)(pr + 12);
                #pragma unroll
                for (int bi = 0; bi < 4; bi++) {
                    float he = wa0.x*xa[bi].x + wa0.y*xa[bi].y + wa0.z*xa[bi].z + wa0.w*xa[bi].w
                             + wb0.x*xb[bi].x + wb0.y*xb[bi].y + wb0.z*xb[bi].z + wb0.w*xb[bi].w;
                    float ho = wa1.x*xa[bi].x + wa1.y*xa[bi].y + wa1.z*xa[bi].z + wa1.w*xa[bi].w
                             + wb1.x*xb[bi].x + wb1.y*xb[bi].y + wb1.z*xb[bi].z + wb1.w*xb[bi].w;
                    sacc[bi][4] += he;
                    sacc[bi][5] += ho;
                    *(__half2*)(hp0 + (size_t)bi * (II * OD) + 2 * p) =
                        __floats2half2_rn(he, ho);
                }
            }
        }
        __syncthreads();
    }
    #pragma unroll
    for (int bi = 0; bi < 4; bi++) {
        float* sp = g_spart + ((size_t)(b0 + bi) * NTMAX + blockIdx.x) * OD;
        *(float2*)(sp + 2 * lane)      = make_float2(0.1f * sacc[bi][0], 0.1f * sacc[bi][1]);
        *(float2*)(sp + 64 + 2 * lane) = make_float2(0.1f * sacc[bi][2], 0.1f * sacc[bi][3]);
        if (lane < 16)
            *(float2*)(sp + 128 + 2 * lane) = make_float2(0.1f * sacc[bi][4], 0.1f * sacc[bi][5]);
    }
}

// K2: routing pass, o-per-lane. Lane = (bh, o): lanes 0-9 & 16-25 active.
__global__ void __launch_bounds__(256) k_route() {
    const int t = threadIdx.x;
    const int warp = t >> 5, lane = t & 31;
    const int o = lane & 15;
    const bool act = (o < OO);
    const int b = blockIdx.y * 16 + warp * 2 + (lane >> 4);
    const int i0 = blockIdx.x * ITR;

    float v[16];
    const float* vp = g_vsum + b * OD + o * DDO;
    if (act) {
        #pragma unroll
        for (int r = 0; r < 4; r++) {
            float4 f = *(const float4*)(vp + 4 * r);
            v[4*r] = f.x; v[4*r+1] = f.y; v[4*r+2] = f.z; v[4*r+3] = f.w;
        }
    } else {
        #pragma unroll
        for (int k = 0; k < 16; k++) v[k] = 0.f;
    }

    float sacc[16];
    #pragma unroll
    for (int k = 0; k < 16; k++) sacc[k] = 0.f;

    #pragma unroll 2
    for (int ii = 0; ii < ITR; ii++) {
        const __half* hp = g_hat + ((size_t)b * II + (i0 + ii)) * OD + o * DDO;
        float h[16];
        float e = 0.f;
        if (act) {
            uint4 ra = *(const uint4*)hp;
            uint4 rb = *(const uint4*)(hp + 8);
            const __half2* pa = (const __half2*)&ra;
            const __half2* pb = (const __half2*)&rb;
            #pragma unroll
            for (int k = 0; k < 4; k++) {
                float2 fa = __half22float2(pa[k]);
                float2 fb = __half22float2(pb[k]);
                h[2*k]   = fa.x; h[2*k+1]   = fa.y;
                h[8+2*k] = fb.x; h[8+2*k+1] = fb.y;
            }
            float q = 0.f;
            #pragma unroll
            for (int k = 0; k < 16; k++) q += h[k] * v[k];
            e = __expf(q);                      // unstabilized, |q| small
        } else {
            #pragma unroll
            for (int k = 0; k < 16; k++) h[k] = 0.f;
        }
        float tot = e;
        #pragma unroll
        for (int s = 8; s >= 1; s >>= 1)
            tot += __shfl_xor_sync(0xffffffffu, tot, s);
        const float c = e * (1.0f / tot);
        #pragma unroll
        for (int k = 0; k < 16; k++) sacc[k] += c * h[k];
    }

    if (act) {
        float* sp = g_spart + ((size_t)b * NTMAX + blockIdx.x) * OD + o * DDO;
        #pragma unroll
        for (int r = 0; r < 4; r++)
            *(float4*)(sp + 4 * r) = make_float4(sacc[4*r], sacc[4*r+1],
                                                 sacc[4*r+2], sacc[4*r+3]);
    }
}

// K3: fixed-order partial reduction + squash. Warp per (b,o); lane = (tc, d).
__global__ void __launch_bounds__(256) k_squash(float* __restrict__ out, int mode,
                                                int ntiles) {
    const int t = threadIdx.x;
    const int warp = t >> 5, lane = t & 31;
    const int g = blockIdx.x * 8 + warp;       // (b,o), 2560 total
    const int d = lane & 15, tc = lane >> 4;
    const int b = g / OO, o = g - b * OO;
    const int od = o * DDO + d;

    float sh = 0.f;
    for (int tt = tc; tt < ntiles; tt += 2)
        sh += g_spart[((size_t)b * NTMAX + tt) * OD + od];
    const float s = sh + __shfl_xor_sync(0xffffffffu, sh, 16);

    float ss = s * s;
    #pragma unroll
    for (int r = 8; r >= 1; r >>= 1)
        ss += __shfl_xor_sync(0xffffffffu, ss, r);

    const float nrm = sqrtf(ss);
    const float v = s * (nrm / (nrm * nrm + 1.0f));
    if (tc == 0) {
        const int idx = b * OD + od;
        if (mode == 2)      out[idx] = v;
        else if (mode == 1) g_vsum[idx] += v;
        else                g_vsum[idx] = v;
    }
}

extern "C" void kernel_launch(void* const* d_in, const int* in_sizes, int n_in,
                              void* d_out, int out_size) {
    const float* x = (const float*)d_in[0];   // (B, I, DI)
    const float* w = (const float*)d_in[1];   // (I*O, DO, DI)
    float* out = (float*)d_out;               // (B, O, DO)

    dim3 ghat(NTH, BB / 32);
    dim3 grt(NTR, BB / 16);

    k_hat<<<ghat, 256>>>(x, w);
    k_squash<<<320, 256>>>(out, 0, NTH);   // v0 -> vsum
    k_route<<<grt, 256>>>();               // iter 1
    k_squash<<<320, 256>>>(out, 1, NTR);   // v1 -> vsum
    k_route<<<grt, 256>>>();               // iter 2
    k_squash<<<320, 256>>>(out, 2, NTR);   // v2 -> out
}